// round 1
// baseline (speedup 1.0000x reference)
#include <cuda_runtime.h>
#include <math.h>

#define BATCH   4
#define NTOK    512
#define DMODEL  512
#define NH      8
#define DKH     64

// ---------------- device scratch (no allocations allowed) ----------------
__device__ float g_Q[BATCH*NH*NTOK*DKH];     // 4 MB  [b][h][n][dk]
__device__ float g_K[BATCH*NH*NTOK*DKH];     // 4 MB
__device__ float g_V[BATCH*NH*NTOK*DKH];     // 4 MB
__device__ float g_BIAS[BATCH*NH*NTOK*NTOK]; // 32 MB [b][h][i][j] = log(max(relu(wg),1e-6))
__device__ float g_CTX[BATCH*NTOK*DMODEL];   // 4 MB  [b][n][h*64+d]

// =====================================================================
// Kernel 1: geometry bias.
// grid (NTOK, BATCH), 256 threads. Block handles query row i of batch b.
// =====================================================================
__global__ void geom_kernel(const float* __restrict__ box,
                            const float* __restrict__ WG,
                            const float* __restrict__ bG)
{
    __shared__ float sWGs[32][8];  // sin weights transposed [t][h]
    __shared__ float sWGc[32][8];  // cos weights
    __shared__ float sbG[8];

    const int b = blockIdx.y;
    const int i = blockIdx.x;
    const int tid = threadIdx.x;

    for (int e = tid; e < 512; e += blockDim.x) {
        int h = e >> 6, g = e & 63;
        float v = WG[e];
        if (g < 32) sWGs[g][h] = v;
        else        sWGc[g - 32][h] = v;
    }
    if (tid < 8) sbG[tid] = bG[tid];

    const float4 bi = *(const float4*)(box + ((long)b*NTOK + i)*4);
    const float cxi = 0.5f*(bi.x + bi.z);
    const float cyi = 0.5f*(bi.y + bi.w);
    const float wi  = bi.z - bi.x + 1.0f;
    const float hi  = bi.w - bi.y + 1.0f;
    const float lwi = logf(wi);
    const float lhi = logf(hi);
    __syncthreads();

    // dim_mat = 1000^{-r/8}
    const float dm[8] = {1.0f, 0.4216965034f, 0.1778279410f, 0.0749894209f,
                         0.0316227766f, 0.0133352143f, 0.0056234133f, 0.0023713737f};

    float* outb = g_BIAS + ((long)b*NH*NTOK + i)*NTOK;  // + h*NTOK*NTOK + j

    for (int j = tid; j < NTOK; j += blockDim.x) {
        float4 bj = *(const float4*)(box + ((long)b*NTOK + j)*4);
        float cxj = 0.5f*(bj.x + bj.z);
        float cyj = 0.5f*(bj.y + bj.w);
        float wj  = bj.z - bj.x + 1.0f;
        float hj  = bj.w - bj.y + 1.0f;

        float a0 = 100.0f * logf(fmaxf(fabsf(cxi - cxj) / wi, 1e-3f));
        float a1 = 100.0f * logf(fmaxf(fabsf(cyi - cyj) / hi, 1e-3f));
        float a2 = 100.0f * (lwi - logf(wj));
        float a3 = 100.0f * (lhi - logf(hj));
        float a[4] = {a0, a1, a2, a3};

        float acc[8];
        #pragma unroll
        for (int h = 0; h < 8; h++) acc[h] = sbG[h];

        #pragma unroll
        for (int f = 0; f < 4; f++) {
            #pragma unroll
            for (int r = 0; r < 8; r++) {
                float s, c;
                sincosf(a[f] * dm[r], &s, &c);
                const int t = f*8 + r;
                #pragma unroll
                for (int h = 0; h < 8; h++)
                    acc[h] += s * sWGs[t][h] + c * sWGc[t][h];
            }
        }
        #pragma unroll
        for (int h = 0; h < 8; h++) {
            float wg = fmaxf(acc[h], 1e-6f);   // relu then clip(1e-6) == max(x, 1e-6)
            outb[(long)h*NTOK*NTOK + j] = logf(wg);
        }
    }
}

// =====================================================================
// Kernel 2: GEMM  Y[m][c] = sum_k X[m][k]*W[c][k] + bias[c]
// M=2048, K=512, NC=512. Tile 128x64, BK=16, 256 threads, 8x4/thread.
// MODE 0/1/2: headsplit write to g_Q/g_K/g_V. MODE 3: X=g_CTX, plain Y=param.
// =====================================================================
template<int MODE>
__global__ void gemm_kernel(const float* __restrict__ Xin,
                            const float* __restrict__ W,
                            const float* __restrict__ bias,
                            float* __restrict__ Yout)
{
    __shared__ float As[16][132];  // [k][m]
    __shared__ float Bs[16][68];   // [k][n]

    const float* X = (MODE == 3) ? g_CTX : Xin;

    const int tid = threadIdx.x;
    const int tx = tid & 15, ty = tid >> 4;
    const int m0 = blockIdx.y * 128;
    const int n0 = blockIdx.x * 64;

    const int lm = tid >> 1;          // 0..127
    const int lk = (tid & 1) * 8;     // 0 or 8
    const int wn = tid >> 2;          // 0..63
    const int wk = (tid & 3) * 4;     // 0,4,8,12

    float acc[8][4];
    #pragma unroll
    for (int i = 0; i < 8; i++)
        #pragma unroll
        for (int j = 0; j < 4; j++) acc[i][j] = 0.0f;

    for (int k0 = 0; k0 < 512; k0 += 16) {
        float4 xa = *(const float4*)(X + (long)(m0+lm)*512 + k0 + lk);
        float4 xb = *(const float4*)(X + (long)(m0+lm)*512 + k0 + lk + 4);
        As[lk+0][lm]=xa.x; As[lk+1][lm]=xa.y; As[lk+2][lm]=xa.z; As[lk+3][lm]=xa.w;
        As[lk+4][lm]=xb.x; As[lk+5][lm]=xb.y; As[lk+6][lm]=xb.z; As[lk+7][lm]=xb.w;

        float4 wv = *(const float4*)(W + (long)(n0+wn)*512 + k0 + wk);
        Bs[wk+0][wn]=wv.x; Bs[wk+1][wn]=wv.y; Bs[wk+2][wn]=wv.z; Bs[wk+3][wn]=wv.w;
        __syncthreads();

        #pragma unroll
        for (int k = 0; k < 16; k++) {
            float a[8], bb[4];
            *(float4*)&a[0] = *(const float4*)&As[k][ty*8];
            *(float4*)&a[4] = *(const float4*)&As[k][ty*8 + 4];
            *(float4*)&bb[0] = *(const float4*)&Bs[k][tx*4];
            #pragma unroll
            for (int i = 0; i < 8; i++)
                #pragma unroll
                for (int j = 0; j < 4; j++)
                    acc[i][j] = fmaf(a[i], bb[j], acc[i][j]);
        }
        __syncthreads();
    }

    float4 bi4 = *(const float4*)(bias + n0 + tx*4);
    const float bb[4] = {bi4.x, bi4.y, bi4.z, bi4.w};

    if (MODE == 3) {
        #pragma unroll
        for (int i = 0; i < 8; i++) {
            int m = m0 + ty*8 + i;
            float4 r;
            r.x = acc[i][0] + bb[0]; r.y = acc[i][1] + bb[1];
            r.z = acc[i][2] + bb[2]; r.w = acc[i][3] + bb[3];
            *(float4*)(Yout + (long)m*512 + n0 + tx*4) = r;
        }
    } else {
        float* Y = (MODE == 0) ? g_Q : (MODE == 1) ? g_K : g_V;
        const int h = n0 >> 6;   // BN=64 == DKH, so one head per block column
        #pragma unroll
        for (int i = 0; i < 8; i++) {
            int m = m0 + ty*8 + i;
            int b = m >> 9, n = m & 511;
            float4 r;
            r.x = acc[i][0] + bb[0]; r.y = acc[i][1] + bb[1];
            r.z = acc[i][2] + bb[2]; r.w = acc[i][3] + bb[3];
            *(float4*)(Y + (((long)(b*NH + h)*NTOK + n)*DKH) + tx*4) = r;
        }
    }
}

// =====================================================================
// Kernel 3: attention. grid (B*H, N/64), 256 threads, 184320 B dyn smem.
// Materializes full 64x512 logits in smem, exact softmax, then PV.
// =====================================================================
__global__ void attn_kernel()
{
    extern __shared__ float sm[];
    float* S  = sm;                   // [64][516]
    float* Qs = sm + 64*516;          // [64][68]  (k-major: Qs[k][m])
    float* Ks = Qs + 64*68;           // [64][68]  (k-major: Ks[k][n])
    float* Vs = Ks + 64*68;           // [64][68]  (n-major: Vs[n][d])

    const int tid = threadIdx.x;
    const int tx = tid & 15, ty = tid >> 4;
    const int bh = blockIdx.x;
    const int q0 = blockIdx.y * 64;

    const float* Qg = g_Q   + (long)bh*NTOK*DKH + (long)q0*DKH;
    const float* Kg = g_K   + (long)bh*NTOK*DKH;
    const float* Vg = g_V   + (long)bh*NTOK*DKH;
    const float* Bg = g_BIAS + (long)bh*NTOK*NTOK + (long)q0*NTOK;

    // load Q tile transposed into Qs[k][m]
    {
        int m = tid >> 2;
        int kq = (tid & 3) * 16;
        const float* src = Qg + m*64 + kq;
        #pragma unroll
        for (int u = 0; u < 4; u++) {
            float4 v = *(const float4*)(src + u*4);
            Qs[(kq+u*4+0)*68 + m] = v.x;
            Qs[(kq+u*4+1)*68 + m] = v.y;
            Qs[(kq+u*4+2)*68 + m] = v.z;
            Qs[(kq+u*4+3)*68 + m] = v.w;
        }
    }

    const int my = ty*4, nx = tx*4;

    // ---- scores + bias into S ----
    for (int t = 0; t < 8; t++) {
        __syncthreads();
        {
            int n = tid >> 2;
            int kq = (tid & 3) * 16;
            const float* src = Kg + (long)(t*64 + n)*64 + kq;
            #pragma unroll
            for (int u = 0; u < 4; u++) {
                float4 v = *(const float4*)(src + u*4);
                Ks[(kq+u*4+0)*68 + n] = v.x;
                Ks[(kq+u*4+1)*68 + n] = v.y;
                Ks[(kq+u*4+2)*68 + n] = v.z;
                Ks[(kq+u*4+3)*68 + n] = v.w;
            }
        }
        __syncthreads();

        float sacc[4][4];
        #pragma unroll
        for (int i = 0; i < 4; i++)
            #pragma unroll
            for (int j = 0; j < 4; j++) sacc[i][j] = 0.0f;

        #pragma unroll 4
        for (int k = 0; k < 64; k++) {
            float4 av = *(const float4*)&Qs[k*68 + my];
            float4 bv = *(const float4*)&Ks[k*68 + nx];
            float a[4] = {av.x, av.y, av.z, av.w};
            float b[4] = {bv.x, bv.y, bv.z, bv.w};
            #pragma unroll
            for (int i = 0; i < 4; i++)
                #pragma unroll
                for (int j = 0; j < 4; j++)
                    sacc[i][j] = fmaf(a[i], b[j], sacc[i][j]);
        }
        #pragma unroll
        for (int i = 0; i < 4; i++) {
            float4 b4 = *(const float4*)(Bg + (long)(my+i)*512 + t*64 + nx);
            float4 r;
            r.x = sacc[i][0]*0.125f + b4.x;
            r.y = sacc[i][1]*0.125f + b4.y;
            r.z = sacc[i][2]*0.125f + b4.z;
            r.w = sacc[i][3]*0.125f + b4.w;
            *(float4*)&S[(my+i)*516 + t*64 + nx] = r;
        }
    }
    __syncthreads();

    // ---- softmax over 512 columns, one warp handles 8 rows ----
    {
        const int wid = tid >> 5, lane = tid & 31;
        for (int r = wid; r < 64; r += 8) {
            float* row = S + r*516;
            float mx = -1e30f;
            for (int c = lane; c < 512; c += 32) mx = fmaxf(mx, row[c]);
            #pragma unroll
            for (int o = 16; o > 0; o >>= 1) mx = fmaxf(mx, __shfl_xor_sync(0xffffffffu, mx, o));
            float sum = 0.0f;
            for (int c = lane; c < 512; c += 32) {
                float p = expf(row[c] - mx);
                row[c] = p;
                sum += p;
            }
            #pragma unroll
            for (int o = 16; o > 0; o >>= 1) sum += __shfl_xor_sync(0xffffffffu, sum, o);
            float inv = 1.0f / sum;
            for (int c = lane; c < 512; c += 32) row[c] *= inv;
        }
    }
    __syncthreads();

    // ---- O = P @ V ----
    float oacc[4][4];
    #pragma unroll
    for (int i = 0; i < 4; i++)
        #pragma unroll
        for (int j = 0; j < 4; j++) oacc[i][j] = 0.0f;

    for (int t = 0; t < 8; t++) {
        if (t) __syncthreads();
        {
            int n = tid >> 2;
            int dq = (tid & 3) * 16;
            const float* src = Vg + (long)(t*64 + n)*64 + dq;
            #pragma unroll
            for (int u = 0; u < 4; u++)
                *(float4*)&Vs[n*68 + dq + u*4] = *(const float4*)(src + u*4);
        }
        __syncthreads();

        #pragma unroll 4
        for (int n = 0; n < 64; n++) {
            float4 vv = *(const float4*)&Vs[n*68 + nx];
            float v[4] = {vv.x, vv.y, vv.z, vv.w};
            float p[4];
            #pragma unroll
            for (int i = 0; i < 4; i++) p[i] = S[(my+i)*516 + t*64 + n];
            #pragma unroll
            for (int i = 0; i < 4; i++)
                #pragma unroll
                for (int j = 0; j < 4; j++)
                    oacc[i][j] = fmaf(p[i], v[j], oacc[i][j]);
        }
    }

    const int b = bh >> 3, h = bh & 7;
    #pragma unroll
    for (int i = 0; i < 4; i++) {
        int qrow = q0 + my + i;
        float4 r;
        r.x = oacc[i][0]; r.y = oacc[i][1]; r.z = oacc[i][2]; r.w = oacc[i][3];
        *(float4*)(g_CTX + ((long)(b*NTOK + qrow))*512 + h*64 + nx) = r;
    }
}

// =====================================================================
// launch
// =====================================================================
extern "C" void kernel_launch(void* const* d_in, const int* in_sizes, int n_in,
                              void* d_out, int out_size)
{
    const float* in_q  = (const float*)d_in[0];
    const float* in_k  = (const float*)d_in[1];
    const float* in_v  = (const float*)d_in[2];
    const float* box   = (const float*)d_in[3];
    const float* Wq    = (const float*)d_in[4];
    const float* bq    = (const float*)d_in[5];
    const float* Wk    = (const float*)d_in[6];
    const float* bk    = (const float*)d_in[7];
    const float* Wv    = (const float*)d_in[8];
    const float* bv    = (const float*)d_in[9];
    const float* Wo    = (const float*)d_in[10];
    const float* bo    = (const float*)d_in[11];
    const float* WG    = (const float*)d_in[12];
    const float* bG    = (const float*)d_in[13];
    float* out = (float*)d_out;

    const int ATTN_SMEM = (64*516 + 3*64*68) * (int)sizeof(float);  // 184320
    cudaFuncSetAttribute(attn_kernel, cudaFuncAttributeMaxDynamicSharedMemorySize, ATTN_SMEM);

    // geometry bias (independent of projections)
    geom_kernel<<<dim3(NTOK, BATCH), 256>>>(box, WG, bG);

    // Q/K/V projections (head-split outputs)
    dim3 ggrid(512/64, 2048/128);
    gemm_kernel<0><<<ggrid, 256>>>(in_q, Wq, bq, nullptr);
    gemm_kernel<1><<<ggrid, 256>>>(in_k, Wk, bk, nullptr);
    gemm_kernel<2><<<ggrid, 256>>>(in_v, Wv, bv, nullptr);

    // attention
    attn_kernel<<<dim3(BATCH*NH, NTOK/64), 256, ATTN_SMEM>>>();

    // output projection -> d_out
    gemm_kernel<3><<<ggrid, 256>>>(nullptr, Wo, bo, out);
}

// round 2
// speedup vs baseline: 1.2298x; 1.2298x over previous
#include <cuda_runtime.h>
#include <math.h>

#define BATCH   4
#define NTOK    512
#define DMODEL  512
#define NH      8
#define DKH     64

// ---------------- device scratch (no allocations allowed) ----------------
__device__ float g_Q[BATCH*NH*NTOK*DKH];     // 4 MB  [b][h][n][dk]
__device__ float g_K[BATCH*NH*NTOK*DKH];     // 4 MB
__device__ float g_V[BATCH*NH*NTOK*DKH];     // 4 MB
__device__ float g_BIAS[BATCH*NH*NTOK*NTOK]; // 32 MB [b][h][i][j] = log(max(relu(wg),1e-6))
__device__ float g_CTX[BATCH*NTOK*DMODEL];   // 4 MB  [b][n][h*64+d]

// =====================================================================
// Kernel 1: geometry bias.  grid (NTOK, BATCH), 256 threads.
// =====================================================================
__global__ void geom_kernel(const float* __restrict__ box,
                            const float* __restrict__ WG,
                            const float* __restrict__ bG)
{
    __shared__ float sWGs[32][8];
    __shared__ float sWGc[32][8];
    __shared__ float sbG[8];

    const int b = blockIdx.y;
    const int i = blockIdx.x;
    const int tid = threadIdx.x;

    for (int e = tid; e < 512; e += blockDim.x) {
        int h = e >> 6, g = e & 63;
        float v = WG[e];
        if (g < 32) sWGs[g][h] = v;
        else        sWGc[g - 32][h] = v;
    }
    if (tid < 8) sbG[tid] = bG[tid];

    const float4 bi = *(const float4*)(box + ((long)b*NTOK + i)*4);
    const float cxi = 0.5f*(bi.x + bi.z);
    const float cyi = 0.5f*(bi.y + bi.w);
    const float wi  = bi.z - bi.x + 1.0f;
    const float hi  = bi.w - bi.y + 1.0f;
    const float lwi = logf(wi);
    const float lhi = logf(hi);
    __syncthreads();

    const float dm[8] = {1.0f, 0.4216965034f, 0.1778279410f, 0.0749894209f,
                         0.0316227766f, 0.0133352143f, 0.0056234133f, 0.0023713737f};

    float* outb = g_BIAS + ((long)b*NH*NTOK + i)*NTOK;

    for (int j = tid; j < NTOK; j += blockDim.x) {
        float4 bj = *(const float4*)(box + ((long)b*NTOK + j)*4);
        float cxj = 0.5f*(bj.x + bj.z);
        float cyj = 0.5f*(bj.y + bj.w);
        float wj  = bj.z - bj.x + 1.0f;
        float hj  = bj.w - bj.y + 1.0f;

        float a0 = 100.0f * logf(fmaxf(fabsf(cxi - cxj) / wi, 1e-3f));
        float a1 = 100.0f * logf(fmaxf(fabsf(cyi - cyj) / hi, 1e-3f));
        float a2 = 100.0f * (lwi - logf(wj));
        float a3 = 100.0f * (lhi - logf(hj));
        float a[4] = {a0, a1, a2, a3};

        float acc[8];
        #pragma unroll
        for (int h = 0; h < 8; h++) acc[h] = sbG[h];

        #pragma unroll
        for (int f = 0; f < 4; f++) {
            #pragma unroll
            for (int r = 0; r < 8; r++) {
                float s, c;
                sincosf(a[f] * dm[r], &s, &c);
                const int t = f*8 + r;
                #pragma unroll
                for (int h = 0; h < 8; h++)
                    acc[h] += s * sWGs[t][h] + c * sWGc[t][h];
            }
        }
        #pragma unroll
        for (int h = 0; h < 8; h++) {
            float wg = fmaxf(acc[h], 1e-6f);
            outb[(long)h*NTOK*NTOK + j] = logf(wg);
        }
    }
}

// =====================================================================
// Kernel 2a: fused QKV GEMM. grid (8, 16, 3), 256 threads, 2 CTAs/SM.
// Tile 128x64, BK=16, register-prefetch double buffer.
// Y[m][c] = X[m][k] * W[c][k] + b[c], head-split write.
// =====================================================================
__global__ void __launch_bounds__(256, 2) qkv_kernel(
    const float* __restrict__ Xq, const float* __restrict__ Xk, const float* __restrict__ Xv,
    const float* __restrict__ Wq, const float* __restrict__ Wk, const float* __restrict__ Wv,
    const float* __restrict__ bq, const float* __restrict__ bk, const float* __restrict__ bv)
{
    __shared__ float As[16][132];
    __shared__ float Bs[16][68];

    const int z = blockIdx.z;
    const float* X    = (z == 0) ? Xq : (z == 1) ? Xk : Xv;
    const float* W    = (z == 0) ? Wq : (z == 1) ? Wk : Wv;
    const float* bias = (z == 0) ? bq : (z == 1) ? bk : bv;
    float*       Y    = (z == 0) ? g_Q : (z == 1) ? g_K : g_V;

    const int tid = threadIdx.x;
    const int tx = tid & 15, ty = tid >> 4;
    const int m0 = blockIdx.y * 128;
    const int n0 = blockIdx.x * 64;

    const int lm = tid >> 1;
    const int lk = (tid & 1) * 8;
    const int wn = tid >> 2;
    const int wk = (tid & 3) * 4;

    const float* Aptr = X + (long)(m0 + lm)*512 + lk;
    const float* Bptr = W + (long)(n0 + wn)*512 + wk;

    float4 xa = *(const float4*)(Aptr);
    float4 xb = *(const float4*)(Aptr + 4);
    float4 wv = *(const float4*)(Bptr);

    float acc[8][4];
    #pragma unroll
    for (int i = 0; i < 8; i++)
        #pragma unroll
        for (int j = 0; j < 4; j++) acc[i][j] = 0.0f;

    for (int k0 = 0; k0 < 512; k0 += 16) {
        As[lk+0][lm]=xa.x; As[lk+1][lm]=xa.y; As[lk+2][lm]=xa.z; As[lk+3][lm]=xa.w;
        As[lk+4][lm]=xb.x; As[lk+5][lm]=xb.y; As[lk+6][lm]=xb.z; As[lk+7][lm]=xb.w;
        Bs[wk+0][wn]=wv.x; Bs[wk+1][wn]=wv.y; Bs[wk+2][wn]=wv.z; Bs[wk+3][wn]=wv.w;
        __syncthreads();

        if (k0 + 16 < 512) {
            xa = *(const float4*)(Aptr + k0 + 16);
            xb = *(const float4*)(Aptr + k0 + 20);
            wv = *(const float4*)(Bptr + k0 + 16);
        }

        #pragma unroll
        for (int k = 0; k < 16; k++) {
            float a[8], bb[4];
            *(float4*)&a[0] = *(const float4*)&As[k][ty*8];
            *(float4*)&a[4] = *(const float4*)&As[k][ty*8 + 4];
            *(float4*)&bb[0] = *(const float4*)&Bs[k][tx*4];
            #pragma unroll
            for (int i = 0; i < 8; i++)
                #pragma unroll
                for (int j = 0; j < 4; j++)
                    acc[i][j] = fmaf(a[i], bb[j], acc[i][j]);
        }
        __syncthreads();
    }

    float4 bi4 = *(const float4*)(bias + n0 + tx*4);
    const float bb[4] = {bi4.x, bi4.y, bi4.z, bi4.w};

    const int h = n0 >> 6;
    #pragma unroll
    for (int i = 0; i < 8; i++) {
        int m = m0 + ty*8 + i;
        int b = m >> 9, n = m & 511;
        float4 r;
        r.x = acc[i][0] + bb[0]; r.y = acc[i][1] + bb[1];
        r.z = acc[i][2] + bb[2]; r.w = acc[i][3] + bb[3];
        *(float4*)(Y + (((long)(b*NH + h)*NTOK + n)*DKH) + tx*4) = r;
    }
}

// =====================================================================
// Kernel 2b: output projection. grid (8, 16), 256 threads.
// Same tiling + prefetch; X = g_CTX, plain row write.
// =====================================================================
__global__ void __launch_bounds__(256, 2) oproj_kernel(
    const float* __restrict__ W, const float* __restrict__ bias,
    float* __restrict__ Yout)
{
    __shared__ float As[16][132];
    __shared__ float Bs[16][68];

    const float* X = g_CTX;
    const int tid = threadIdx.x;
    const int tx = tid & 15, ty = tid >> 4;
    const int m0 = blockIdx.y * 128;
    const int n0 = blockIdx.x * 64;

    const int lm = tid >> 1;
    const int lk = (tid & 1) * 8;
    const int wn = tid >> 2;
    const int wk = (tid & 3) * 4;

    const float* Aptr = X + (long)(m0 + lm)*512 + lk;
    const float* Bptr = W + (long)(n0 + wn)*512 + wk;

    float4 xa = *(const float4*)(Aptr);
    float4 xb = *(const float4*)(Aptr + 4);
    float4 wv = *(const float4*)(Bptr);

    float acc[8][4];
    #pragma unroll
    for (int i = 0; i < 8; i++)
        #pragma unroll
        for (int j = 0; j < 4; j++) acc[i][j] = 0.0f;

    for (int k0 = 0; k0 < 512; k0 += 16) {
        As[lk+0][lm]=xa.x; As[lk+1][lm]=xa.y; As[lk+2][lm]=xa.z; As[lk+3][lm]=xa.w;
        As[lk+4][lm]=xb.x; As[lk+5][lm]=xb.y; As[lk+6][lm]=xb.z; As[lk+7][lm]=xb.w;
        Bs[wk+0][wn]=wv.x; Bs[wk+1][wn]=wv.y; Bs[wk+2][wn]=wv.z; Bs[wk+3][wn]=wv.w;
        __syncthreads();

        if (k0 + 16 < 512) {
            xa = *(const float4*)(Aptr + k0 + 16);
            xb = *(const float4*)(Aptr + k0 + 20);
            wv = *(const float4*)(Bptr + k0 + 16);
        }

        #pragma unroll
        for (int k = 0; k < 16; k++) {
            float a[8], bb[4];
            *(float4*)&a[0] = *(const float4*)&As[k][ty*8];
            *(float4*)&a[4] = *(const float4*)&As[k][ty*8 + 4];
            *(float4*)&bb[0] = *(const float4*)&Bs[k][tx*4];
            #pragma unroll
            for (int i = 0; i < 8; i++)
                #pragma unroll
                for (int j = 0; j < 4; j++)
                    acc[i][j] = fmaf(a[i], bb[j], acc[i][j]);
        }
        __syncthreads();
    }

    float4 bi4 = *(const float4*)(bias + n0 + tx*4);
    const float bb[4] = {bi4.x, bi4.y, bi4.z, bi4.w};

    #pragma unroll
    for (int i = 0; i < 8; i++) {
        int m = m0 + ty*8 + i;
        float4 r;
        r.x = acc[i][0] + bb[0]; r.y = acc[i][1] + bb[1];
        r.z = acc[i][2] + bb[2]; r.w = acc[i][3] + bb[3];
        *(float4*)(Yout + (long)m*512 + n0 + tx*4) = r;
    }
}

// =====================================================================
// Kernel 3: flash-style attention. grid (B*H, N/64), 256 threads,
// 68 KB dyn smem (2 CTAs/SM). Online softmax, no full score strip.
// =====================================================================
__global__ void __launch_bounds__(256, 2) attn_kernel()
{
    extern __shared__ float sm[];
    float* Qs = sm;             // [64][68] Qs[k][m] (pre-scaled by 1/8)
    float* Ks = Qs + 64*68;     // [64][68] Ks[k][n]
    float* Vs = Ks + 64*68;     // [64][68] Vs[n][d]
    float* Ps = Vs + 64*68;     // [64][68] Ps[m][n]

    const int tid = threadIdx.x;
    const int tx = tid & 15, ty = tid >> 4;
    const int bh = blockIdx.x;
    const int q0 = blockIdx.y * 64;

    const float* Qg = g_Q   + (long)bh*NTOK*DKH + (long)q0*DKH;
    const float* Kg = g_K   + (long)bh*NTOK*DKH;
    const float* Vg = g_V   + (long)bh*NTOK*DKH;
    const float* Bg = g_BIAS + (long)bh*NTOK*NTOK + (long)q0*NTOK;

    // load Q tile transposed, folding the 1/sqrt(64)=0.125 scale
    {
        int m = tid >> 2;
        int kq = (tid & 3) * 16;
        const float* src = Qg + m*64 + kq;
        #pragma unroll
        for (int u = 0; u < 4; u++) {
            float4 v = *(const float4*)(src + u*4);
            Qs[(kq+u*4+0)*68 + m] = v.x * 0.125f;
            Qs[(kq+u*4+1)*68 + m] = v.y * 0.125f;
            Qs[(kq+u*4+2)*68 + m] = v.z * 0.125f;
            Qs[(kq+u*4+3)*68 + m] = v.w * 0.125f;
        }
    }

    const int my = ty*4, nx = tx*4;

    float m_i[4] = {-1e30f, -1e30f, -1e30f, -1e30f};
    float l_i[4] = {0.0f, 0.0f, 0.0f, 0.0f};
    float oacc[4][4];
    #pragma unroll
    for (int i = 0; i < 4; i++)
        #pragma unroll
        for (int j = 0; j < 4; j++) oacc[i][j] = 0.0f;

    for (int t = 0; t < 8; t++) {
        __syncthreads();   // previous tile's QK/PV done (covers Q load on t=0)
        {
            int n = tid >> 2;
            int kq = (tid & 3) * 16;
            const float* srcK = Kg + (long)(t*64 + n)*64 + kq;
            const float* srcV = Vg + (long)(t*64 + n)*64 + kq;
            #pragma unroll
            for (int u = 0; u < 4; u++) {
                float4 v = *(const float4*)(srcK + u*4);
                Ks[(kq+u*4+0)*68 + n] = v.x;
                Ks[(kq+u*4+1)*68 + n] = v.y;
                Ks[(kq+u*4+2)*68 + n] = v.z;
                Ks[(kq+u*4+3)*68 + n] = v.w;
                *(float4*)&Vs[n*68 + kq + u*4] = *(const float4*)(srcV + u*4);
            }
        }
        __syncthreads();

        // --- scores tile: sacc = (Q/8) . K^T + bias ---
        float sacc[4][4];
        #pragma unroll
        for (int i = 0; i < 4; i++)
            #pragma unroll
            for (int j = 0; j < 4; j++) sacc[i][j] = 0.0f;

        #pragma unroll 4
        for (int k = 0; k < 64; k++) {
            float4 av = *(const float4*)&Qs[k*68 + my];
            float4 bv = *(const float4*)&Ks[k*68 + nx];
            float a[4] = {av.x, av.y, av.z, av.w};
            float b[4] = {bv.x, bv.y, bv.z, bv.w};
            #pragma unroll
            for (int i = 0; i < 4; i++)
                #pragma unroll
                for (int j = 0; j < 4; j++)
                    sacc[i][j] = fmaf(a[i], b[j], sacc[i][j]);
        }
        #pragma unroll
        for (int i = 0; i < 4; i++) {
            float4 b4 = *(const float4*)(Bg + (long)(my+i)*512 + t*64 + nx);
            sacc[i][0] += b4.x; sacc[i][1] += b4.y;
            sacc[i][2] += b4.z; sacc[i][3] += b4.w;
        }

        // --- online softmax update ---
        float rsum[4];
        #pragma unroll
        for (int i = 0; i < 4; i++) {
            float tm = fmaxf(fmaxf(sacc[i][0], sacc[i][1]),
                             fmaxf(sacc[i][2], sacc[i][3]));
            #pragma unroll
            for (int o = 1; o < 16; o <<= 1)
                tm = fmaxf(tm, __shfl_xor_sync(0xffffffffu, tm, o));
            float mnew = fmaxf(m_i[i], tm);
            float scale = __expf(m_i[i] - mnew);
            m_i[i] = mnew;

            float s = 0.0f;
            #pragma unroll
            for (int j = 0; j < 4; j++) {
                float p = __expf(sacc[i][j] - mnew);
                sacc[i][j] = p;
                s += p;
            }
            #pragma unroll
            for (int o = 1; o < 16; o <<= 1)
                s += __shfl_xor_sync(0xffffffffu, s, o);
            l_i[i] = l_i[i]*scale + s;

            #pragma unroll
            for (int j = 0; j < 4; j++) oacc[i][j] *= scale;

            *(float4*)&Ps[(my+i)*68 + nx] = *(float4*)&sacc[i][0];
        }
        __syncthreads();

        // --- O += P @ V ---
        #pragma unroll 4
        for (int n = 0; n < 64; n++) {
            float4 vv = *(const float4*)&Vs[n*68 + nx];
            float v[4] = {vv.x, vv.y, vv.z, vv.w};
            float p[4];
            #pragma unroll
            for (int i = 0; i < 4; i++) p[i] = Ps[(my+i)*68 + n];
            #pragma unroll
            for (int i = 0; i < 4; i++)
                #pragma unroll
                for (int j = 0; j < 4; j++)
                    oacc[i][j] = fmaf(p[i], v[j], oacc[i][j]);
        }
    }

    const int b = bh >> 3, h = bh & 7;
    #pragma unroll
    for (int i = 0; i < 4; i++) {
        float inv = 1.0f / l_i[i];
        int qrow = q0 + my + i;
        float4 r;
        r.x = oacc[i][0]*inv; r.y = oacc[i][1]*inv;
        r.z = oacc[i][2]*inv; r.w = oacc[i][3]*inv;
        *(float4*)(g_CTX + ((long)(b*NTOK + qrow))*512 + h*64 + nx) = r;
    }
}

// =====================================================================
// launch
// =====================================================================
extern "C" void kernel_launch(void* const* d_in, const int* in_sizes, int n_in,
                              void* d_out, int out_size)
{
    const float* in_q  = (const float*)d_in[0];
    const float* in_k  = (const float*)d_in[1];
    const float* in_v  = (const float*)d_in[2];
    const float* box   = (const float*)d_in[3];
    const float* Wq    = (const float*)d_in[4];
    const float* bq    = (const float*)d_in[5];
    const float* Wk    = (const float*)d_in[6];
    const float* bk    = (const float*)d_in[7];
    const float* Wv    = (const float*)d_in[8];
    const float* bv    = (const float*)d_in[9];
    const float* Wo    = (const float*)d_in[10];
    const float* bo    = (const float*)d_in[11];
    const float* WG    = (const float*)d_in[12];
    const float* bG    = (const float*)d_in[13];
    float* out = (float*)d_out;

    const int ATTN_SMEM = 4 * 64 * 68 * (int)sizeof(float);  // 69632
    cudaFuncSetAttribute(attn_kernel, cudaFuncAttributeMaxDynamicSharedMemorySize, ATTN_SMEM);

    // geometry bias
    geom_kernel<<<dim3(NTOK, BATCH), 256>>>(box, WG, bG);

    // fused Q/K/V projections
    qkv_kernel<<<dim3(512/64, 2048/128, 3), 256>>>(in_q, in_k, in_v,
                                                   Wq, Wk, Wv, bq, bk, bv);

    // attention
    attn_kernel<<<dim3(BATCH*NH, NTOK/64), 256, ATTN_SMEM>>>();

    // output projection -> d_out
    oproj_kernel<<<dim3(512/64, 2048/128), 256>>>(Wo, bo, out);
}

// round 4
// speedup vs baseline: 1.3950x; 1.1344x over previous
#include <cuda_runtime.h>
#include <math.h>

#define BATCH   4
#define NTOK    512
#define DMODEL  512
#define NH      8
#define DKH     64

// ---------------- device scratch (no allocations allowed) ----------------
__device__ float g_Q[BATCH*NH*NTOK*DKH];     // 4 MB  [b][h][n][dk]
__device__ float g_K[BATCH*NH*NTOK*DKH];     // 4 MB
__device__ float g_V[BATCH*NH*NTOK*DKH];     // 4 MB
__device__ float g_BIAS[BATCH*NH*NTOK*NTOK]; // 32 MB
__device__ float g_CTX[BATCH*NTOK*DMODEL];   // 4 MB

// ---------------- helpers ----------------
__device__ __forceinline__ unsigned f2tf32(float x) {
    unsigned b;
    asm("cvt.rna.tf32.f32 %0, %1;" : "=r"(b) : "f"(x));
    return b;
}

__device__ __forceinline__ void mma_tf32(float& c0, float& c1, float& c2, float& c3,
                                         unsigned a0, unsigned a1, unsigned a2, unsigned a3,
                                         unsigned b0, unsigned b1) {
    asm volatile("mma.sync.aligned.m16n8k8.row.col.f32.tf32.tf32.f32 "
                 "{%0,%1,%2,%3}, {%4,%5,%6,%7}, {%8,%9}, {%0,%1,%2,%3};"
                 : "+f"(c0), "+f"(c1), "+f"(c2), "+f"(c3)
                 : "r"(a0), "r"(a1), "r"(a2), "r"(a3), "r"(b0), "r"(b1));
}

// =====================================================================
// Kernel 1: geometry bias.  grid (NTOK, BATCH), 256 threads.
// =====================================================================
__global__ void geom_kernel(const float* __restrict__ box,
                            const float* __restrict__ WG,
                            const float* __restrict__ bG)
{
    __shared__ float sWGs[32][8];
    __shared__ float sWGc[32][8];
    __shared__ float sbG[8];

    const int b = blockIdx.y;
    const int i = blockIdx.x;
    const int tid = threadIdx.x;

    for (int e = tid; e < 512; e += blockDim.x) {
        int h = e >> 6, g = e & 63;
        float v = WG[e];
        if (g < 32) sWGs[g][h] = v;
        else        sWGc[g - 32][h] = v;
    }
    if (tid < 8) sbG[tid] = bG[tid];

    const float4 bi = *(const float4*)(box + ((long)b*NTOK + i)*4);
    const float cxi = 0.5f*(bi.x + bi.z);
    const float cyi = 0.5f*(bi.y + bi.w);
    const float wi  = bi.z - bi.x + 1.0f;
    const float hi  = bi.w - bi.y + 1.0f;
    const float lwi = logf(wi);
    const float lhi = logf(hi);
    __syncthreads();

    const float dm[8] = {1.0f, 0.4216965034f, 0.1778279410f, 0.0749894209f,
                         0.0316227766f, 0.0133352143f, 0.0056234133f, 0.0023713737f};

    float* outb = g_BIAS + ((long)b*NH*NTOK + i)*NTOK;

    for (int j = tid; j < NTOK; j += blockDim.x) {
        float4 bj = *(const float4*)(box + ((long)b*NTOK + j)*4);
        float cxj = 0.5f*(bj.x + bj.z);
        float cyj = 0.5f*(bj.y + bj.w);
        float wj  = bj.z - bj.x + 1.0f;
        float hj  = bj.w - bj.y + 1.0f;

        float a0 = 100.0f * logf(fmaxf(fabsf(cxi - cxj) / wi, 1e-3f));
        float a1 = 100.0f * logf(fmaxf(fabsf(cyi - cyj) / hi, 1e-3f));
        float a2 = 100.0f * (lwi - logf(wj));
        float a3 = 100.0f * (lhi - logf(hj));
        float a[4] = {a0, a1, a2, a3};

        float acc[8];
        #pragma unroll
        for (int h = 0; h < 8; h++) acc[h] = sbG[h];

        #pragma unroll
        for (int f = 0; f < 4; f++) {
            #pragma unroll
            for (int r = 0; r < 8; r++) {
                float s, c;
                sincosf(a[f] * dm[r], &s, &c);
                const int t = f*8 + r;
                #pragma unroll
                for (int h = 0; h < 8; h++)
                    acc[h] += s * sWGs[t][h] + c * sWGc[t][h];
            }
        }
        #pragma unroll
        for (int h = 0; h < 8; h++) {
            float wg = fmaxf(acc[h], 1e-6f);
            outb[(long)h*NTOK*NTOK + j] = logf(wg);
        }
    }
}

// =====================================================================
// TF32 tensor-core GEMM core.
// CTA tile 128(M) x 64(N), BK=16, 256 threads = 8 warps (4x2 warp grid,
// each warp 32x32 via m16n8k8 mma). Y[m][c] = X[m][k]*W[c][k] + bias[c].
// =====================================================================
struct GemmAcc { float c[2][4][4]; };

template<typename WriteFn>
__device__ __forceinline__ void gemm_tf32_core(
    const float* __restrict__ X, const float* __restrict__ W,
    int m0, int n0, WriteFn&& write)
{
    __shared__ float As[16][132];   // [k][m]
    __shared__ float Bs[16][68];    // [k][n]

    const int tid = threadIdx.x;

    const int lm = tid >> 1;           // 0..127
    const int lk = (tid & 1) * 8;      // 0 or 8
    const int wn = tid >> 2;           // 0..63
    const int wk = (tid & 3) * 4;      // 0,4,8,12

    const float* Aptr = X + (long)(m0 + lm)*512 + lk;
    const float* Bptr = W + (long)(n0 + wn)*512 + wk;

    float4 xa = *(const float4*)(Aptr);
    float4 xb = *(const float4*)(Aptr + 4);
    float4 wv = *(const float4*)(Bptr);

    const int w    = tid >> 5;
    const int wm   = (w & 3) * 32;
    const int wn2  = (w >> 2) * 32;
    const int lane = tid & 31;
    const int lr   = lane >> 2;
    const int lc   = lane & 3;

    GemmAcc A;
    #pragma unroll
    for (int mi = 0; mi < 2; mi++)
        #pragma unroll
        for (int ni = 0; ni < 4; ni++)
            #pragma unroll
            for (int q = 0; q < 4; q++) A.c[mi][ni][q] = 0.0f;

    for (int k0 = 0; k0 < 512; k0 += 16) {
        As[lk+0][lm]=__uint_as_float(f2tf32(xa.x));
        As[lk+1][lm]=__uint_as_float(f2tf32(xa.y));
        As[lk+2][lm]=__uint_as_float(f2tf32(xa.z));
        As[lk+3][lm]=__uint_as_float(f2tf32(xa.w));
        As[lk+4][lm]=__uint_as_float(f2tf32(xb.x));
        As[lk+5][lm]=__uint_as_float(f2tf32(xb.y));
        As[lk+6][lm]=__uint_as_float(f2tf32(xb.z));
        As[lk+7][lm]=__uint_as_float(f2tf32(xb.w));
        Bs[wk+0][wn]=__uint_as_float(f2tf32(wv.x));
        Bs[wk+1][wn]=__uint_as_float(f2tf32(wv.y));
        Bs[wk+2][wn]=__uint_as_float(f2tf32(wv.z));
        Bs[wk+3][wn]=__uint_as_float(f2tf32(wv.w));
        __syncthreads();

        if (k0 + 16 < 512) {
            xa = *(const float4*)(Aptr + k0 + 16);
            xb = *(const float4*)(Aptr + k0 + 20);
            wv = *(const float4*)(Bptr + k0 + 16);
        }

        #pragma unroll
        for (int ks = 0; ks < 2; ks++) {
            const int kb = ks * 8;
            unsigned afr[2][4];
            #pragma unroll
            for (int mi = 0; mi < 2; mi++) {
                const int mrow = wm + 16*mi;
                afr[mi][0] = __float_as_uint(As[kb + lc    ][mrow + lr    ]);
                afr[mi][1] = __float_as_uint(As[kb + lc    ][mrow + lr + 8]);
                afr[mi][2] = __float_as_uint(As[kb + lc + 4][mrow + lr    ]);
                afr[mi][3] = __float_as_uint(As[kb + lc + 4][mrow + lr + 8]);
            }
            unsigned bfr[4][2];
            #pragma unroll
            for (int ni = 0; ni < 4; ni++) {
                const int ncol = wn2 + 8*ni;
                bfr[ni][0] = __float_as_uint(Bs[kb + lc    ][ncol + lr]);
                bfr[ni][1] = __float_as_uint(Bs[kb + lc + 4][ncol + lr]);
            }
            #pragma unroll
            for (int mi = 0; mi < 2; mi++)
                #pragma unroll
                for (int ni = 0; ni < 4; ni++)
                    mma_tf32(A.c[mi][ni][0], A.c[mi][ni][1],
                             A.c[mi][ni][2], A.c[mi][ni][3],
                             afr[mi][0], afr[mi][1], afr[mi][2], afr[mi][3],
                             bfr[ni][0], bfr[ni][1]);
        }
        __syncthreads();
    }

    #pragma unroll
    for (int mi = 0; mi < 2; mi++) {
        #pragma unroll
        for (int ni = 0; ni < 4; ni++) {
            const int row = wm + 16*mi + lr;
            const int col = wn2 + 8*ni + 2*lc;
            write(row,     col, A.c[mi][ni][0], A.c[mi][ni][1]);
            write(row + 8, col, A.c[mi][ni][2], A.c[mi][ni][3]);
        }
    }
}

// ---- fused QKV projection (head-split write) ----
__global__ void __launch_bounds__(256) qkv_kernel(
    const float* __restrict__ Xq, const float* __restrict__ Xk, const float* __restrict__ Xv,
    const float* __restrict__ Wq, const float* __restrict__ Wk, const float* __restrict__ Wv,
    const float* __restrict__ bq, const float* __restrict__ bk, const float* __restrict__ bv)
{
    const int z = blockIdx.z;
    const float* X    = (z == 0) ? Xq : (z == 1) ? Xk : Xv;
    const float* W    = (z == 0) ? Wq : (z == 1) ? Wk : Wv;
    const float* bias = (z == 0) ? bq : (z == 1) ? bk : bv;
    float*       Y    = (z == 0) ? g_Q : (z == 1) ? g_K : g_V;

    const int m0 = blockIdx.y * 128;
    const int n0 = blockIdx.x * 64;
    const int h  = n0 >> 6;

    gemm_tf32_core(X, W, m0, n0,
        [&](int row, int col, float v0, float v1) {
            int m = m0 + row;
            int b = m >> 9, n = m & 511;
            float2 r;
            r.x = v0 + bias[n0 + col];
            r.y = v1 + bias[n0 + col + 1];
            *(float2*)(Y + (((long)(b*NH + h)*NTOK + n)*DKH) + col) = r;
        });
}

// ---- output projection ----
__global__ void __launch_bounds__(256) oproj_kernel(
    const float* __restrict__ W, const float* __restrict__ bias,
    float* __restrict__ Yout)
{
    const int m0 = blockIdx.y * 128;
    const int n0 = blockIdx.x * 64;

    gemm_tf32_core(g_CTX, W, m0, n0,
        [&](int row, int col, float v0, float v1) {
            float2 r;
            r.x = v0 + bias[n0 + col];
            r.y = v1 + bias[n0 + col + 1];
            *(float2*)(Yout + (long)(m0 + row)*512 + n0 + col) = r;
        });
}

// =====================================================================
// Kernel 3: flash-style attention (fp32 FFMA). grid (B*H, N/64),
// 256 threads, 68 KB dyn smem, 2 CTAs/SM.
// =====================================================================
__global__ void __launch_bounds__(256, 2) attn_kernel()
{
    extern __shared__ float sm[];
    float* Qs = sm;             // [64][68] Qs[k][m] (pre-scaled by 1/8)
    float* Ks = Qs + 64*68;     // [64][68] Ks[k][n]
    float* Vs = Ks + 64*68;     // [64][68] Vs[n][d]
    float* Ps = Vs + 64*68;     // [64][68] Ps[m][n]

    const int tid = threadIdx.x;
    const int tx = tid & 15, ty = tid >> 4;
    const int bh = blockIdx.x;
    const int q0 = blockIdx.y * 64;

    const float* Qg = g_Q   + (long)bh*NTOK*DKH + (long)q0*DKH;
    const float* Kg = g_K   + (long)bh*NTOK*DKH;
    const float* Vg = g_V   + (long)bh*NTOK*DKH;
    const float* Bg = g_BIAS + (long)bh*NTOK*NTOK + (long)q0*NTOK;

    {
        int m = tid >> 2;
        int kq = (tid & 3) * 16;
        const float* src = Qg + m*64 + kq;
        #pragma unroll
        for (int u = 0; u < 4; u++) {
            float4 v = *(const float4*)(src + u*4);
            Qs[(kq+u*4+0)*68 + m] = v.x * 0.125f;
            Qs[(kq+u*4+1)*68 + m] = v.y * 0.125f;
            Qs[(kq+u*4+2)*68 + m] = v.z * 0.125f;
            Qs[(kq+u*4+3)*68 + m] = v.w * 0.125f;
        }
    }

    const int my = ty*4, nx = tx*4;

    float m_i[4] = {-1e30f, -1e30f, -1e30f, -1e30f};
    float l_i[4] = {0.0f, 0.0f, 0.0f, 0.0f};
    float oacc[4][4];
    #pragma unroll
    for (int i = 0; i < 4; i++)
        #pragma unroll
        for (int j = 0; j < 4; j++) oacc[i][j] = 0.0f;

    for (int t = 0; t < 8; t++) {
        __syncthreads();
        {
            int n = tid >> 2;
            int kq = (tid & 3) * 16;
            const float* srcK = Kg + (long)(t*64 + n)*64 + kq;
            const float* srcV = Vg + (long)(t*64 + n)*64 + kq;
            #pragma unroll
            for (int u = 0; u < 4; u++) {
                float4 v = *(const float4*)(srcK + u*4);
                Ks[(kq+u*4+0)*68 + n] = v.x;
                Ks[(kq+u*4+1)*68 + n] = v.y;
                Ks[(kq+u*4+2)*68 + n] = v.z;
                Ks[(kq+u*4+3)*68 + n] = v.w;
                *(float4*)&Vs[n*68 + kq + u*4] = *(const float4*)(srcV + u*4);
            }
        }
        __syncthreads();

        float sacc[4][4];
        #pragma unroll
        for (int i = 0; i < 4; i++)
            #pragma unroll
            for (int j = 0; j < 4; j++) sacc[i][j] = 0.0f;

        #pragma unroll 4
        for (int k = 0; k < 64; k++) {
            float4 av = *(const float4*)&Qs[k*68 + my];
            float4 bv = *(const float4*)&Ks[k*68 + nx];
            float a[4] = {av.x, av.y, av.z, av.w};
            float b[4] = {bv.x, bv.y, bv.z, bv.w};
            #pragma unroll
            for (int i = 0; i < 4; i++)
                #pragma unroll
                for (int j = 0; j < 4; j++)
                    sacc[i][j] = fmaf(a[i], b[j], sacc[i][j]);
        }
        #pragma unroll
        for (int i = 0; i < 4; i++) {
            float4 b4 = *(const float4*)(Bg + (long)(my+i)*512 + t*64 + nx);
            sacc[i][0] += b4.x; sacc[i][1] += b4.y;
            sacc[i][2] += b4.z; sacc[i][3] += b4.w;
        }

        #pragma unroll
        for (int i = 0; i < 4; i++) {
            float tm = fmaxf(fmaxf(sacc[i][0], sacc[i][1]),
                             fmaxf(sacc[i][2], sacc[i][3]));
            #pragma unroll
            for (int o = 1; o < 16; o <<= 1)
                tm = fmaxf(tm, __shfl_xor_sync(0xffffffffu, tm, o));
            float mnew = fmaxf(m_i[i], tm);
            float scale = __expf(m_i[i] - mnew);
            m_i[i] = mnew;

            float s = 0.0f;
            #pragma unroll
            for (int j = 0; j < 4; j++) {
                float p = __expf(sacc[i][j] - mnew);
                sacc[i][j] = p;
                s += p;
            }
            #pragma unroll
            for (int o = 1; o < 16; o <<= 1)
                s += __shfl_xor_sync(0xffffffffu, s, o);
            l_i[i] = l_i[i]*scale + s;

            #pragma unroll
            for (int j = 0; j < 4; j++) oacc[i][j] *= scale;

            *(float4*)&Ps[(my+i)*68 + nx] = *(float4*)&sacc[i][0];
        }
        __syncthreads();

        #pragma unroll 4
        for (int n = 0; n < 64; n++) {
            float4 vv = *(const float4*)&Vs[n*68 + nx];
            float v[4] = {vv.x, vv.y, vv.z, vv.w};
            float p[4];
            #pragma unroll
            for (int i = 0; i < 4; i++) p[i] = Ps[(my+i)*68 + n];
            #pragma unroll
            for (int i = 0; i < 4; i++)
                #pragma unroll
                for (int j = 0; j < 4; j++)
                    oacc[i][j] = fmaf(p[i], v[j], oacc[i][j]);
        }
    }

    const int b = bh >> 3, h = bh & 7;
    #pragma unroll
    for (int i = 0; i < 4; i++) {
        float inv = 1.0f / l_i[i];
        int qrow = q0 + my + i;
        float4 r;
        r.x = oacc[i][0]*inv; r.y = oacc[i][1]*inv;
        r.z = oacc[i][2]*inv; r.w = oacc[i][3]*inv;
        *(float4*)(g_CTX + ((long)(b*NTOK + qrow))*512 + h*64 + nx) = r;
    }
}

// =====================================================================
// launch
// =====================================================================
extern "C" void kernel_launch(void* const* d_in, const int* in_sizes, int n_in,
                              void* d_out, int out_size)
{
    const float* in_q  = (const float*)d_in[0];
    const float* in_k  = (const float*)d_in[1];
    const float* in_v  = (const float*)d_in[2];
    const float* box   = (const float*)d_in[3];
    const float* Wq    = (const float*)d_in[4];
    const float* bq    = (const float*)d_in[5];
    const float* Wk    = (const float*)d_in[6];
    const float* bk    = (const float*)d_in[7];
    const float* Wv    = (const float*)d_in[8];
    const float* bv    = (const float*)d_in[9];
    const float* Wo    = (const float*)d_in[10];
    const float* bo    = (const float*)d_in[11];
    const float* WG    = (const float*)d_in[12];
    const float* bG    = (const float*)d_in[13];
    float* out = (float*)d_out;

    const int ATTN_SMEM = 4 * 64 * 68 * (int)sizeof(float);  // 69632
    cudaFuncSetAttribute(attn_kernel, cudaFuncAttributeMaxDynamicSharedMemorySize, ATTN_SMEM);

    // geometry bias
    geom_kernel<<<dim3(NTOK, BATCH), 256>>>(box, WG, bG);

    // fused Q/K/V projections (tf32 tensor cores)
    qkv_kernel<<<dim3(512/64, 2048/128, 3), 256>>>(in_q, in_k, in_v,
                                                   Wq, Wk, Wv, bq, bk, bv);

    // attention
    attn_kernel<<<dim3(BATCH*NH, NTOK/64), 256, ATTN_SMEM>>>();

    // output projection -> d_out (tf32 tensor cores)
    oproj_kernel<<<dim3(512/64, 2048/128), 256>>>(Wo, bo, out);
}

// round 5
// speedup vs baseline: 1.5154x; 1.0863x over previous
#include <cuda_runtime.h>
#include <math.h>

#define BATCH   4
#define NTOK    512
#define DMODEL  512
#define NH      8
#define DKH     64

// ---------------- device scratch (no allocations allowed) ----------------
__device__ float g_Q[BATCH*NH*NTOK*DKH];     // 4 MB  [b][h][n][dk]
__device__ float g_K[BATCH*NH*NTOK*DKH];     // 4 MB
__device__ float g_V[BATCH*NH*NTOK*DKH];     // 4 MB
__device__ float g_BIAS[BATCH*NH*NTOK*NTOK]; // 32 MB
__device__ float g_CTX[BATCH*NTOK*DMODEL];   // 4 MB

// ---------------- helpers ----------------
__device__ __forceinline__ unsigned f2tf32(float x) {
    unsigned b;
    asm("cvt.rna.tf32.f32 %0, %1;" : "=r"(b) : "f"(x));
    return b;
}
__device__ __forceinline__ float f2tf32f(float x) {
    return __uint_as_float(f2tf32(x));
}

__device__ __forceinline__ void mma_tf32(float& c0, float& c1, float& c2, float& c3,
                                         unsigned a0, unsigned a1, unsigned a2, unsigned a3,
                                         unsigned b0, unsigned b1) {
    asm volatile("mma.sync.aligned.m16n8k8.row.col.f32.tf32.tf32.f32 "
                 "{%0,%1,%2,%3}, {%4,%5,%6,%7}, {%8,%9}, {%0,%1,%2,%3};"
                 : "+f"(c0), "+f"(c1), "+f"(c2), "+f"(c3)
                 : "r"(a0), "r"(a1), "r"(a2), "r"(a3), "r"(b0), "r"(b1));
}

// =====================================================================
// Kernel 1: geometry bias.  grid (NTOK, BATCH), 256 threads.
// =====================================================================
__global__ void geom_kernel(const float* __restrict__ box,
                            const float* __restrict__ WG,
                            const float* __restrict__ bG)
{
    __shared__ float sWGs[32][8];
    __shared__ float sWGc[32][8];
    __shared__ float sbG[8];

    const int b = blockIdx.y;
    const int i = blockIdx.x;
    const int tid = threadIdx.x;

    for (int e = tid; e < 512; e += blockDim.x) {
        int h = e >> 6, g = e & 63;
        float v = WG[e];
        if (g < 32) sWGs[g][h] = v;
        else        sWGc[g - 32][h] = v;
    }
    if (tid < 8) sbG[tid] = bG[tid];

    const float4 bi = *(const float4*)(box + ((long)b*NTOK + i)*4);
    const float cxi = 0.5f*(bi.x + bi.z);
    const float cyi = 0.5f*(bi.y + bi.w);
    const float wi  = bi.z - bi.x + 1.0f;
    const float hi  = bi.w - bi.y + 1.0f;
    const float lwi = logf(wi);
    const float lhi = logf(hi);
    __syncthreads();

    const float dm[8] = {1.0f, 0.4216965034f, 0.1778279410f, 0.0749894209f,
                         0.0316227766f, 0.0133352143f, 0.0056234133f, 0.0023713737f};

    float* outb = g_BIAS + ((long)b*NH*NTOK + i)*NTOK;

    for (int j = tid; j < NTOK; j += blockDim.x) {
        float4 bj = *(const float4*)(box + ((long)b*NTOK + j)*4);
        float cxj = 0.5f*(bj.x + bj.z);
        float cyj = 0.5f*(bj.y + bj.w);
        float wj  = bj.z - bj.x + 1.0f;
        float hj  = bj.w - bj.y + 1.0f;

        float a0 = 100.0f * logf(fmaxf(fabsf(cxi - cxj) / wi, 1e-3f));
        float a1 = 100.0f * logf(fmaxf(fabsf(cyi - cyj) / hi, 1e-3f));
        float a2 = 100.0f * (lwi - logf(wj));
        float a3 = 100.0f * (lhi - logf(hj));
        float a[4] = {a0, a1, a2, a3};

        float acc[8];
        #pragma unroll
        for (int h = 0; h < 8; h++) acc[h] = sbG[h];

        #pragma unroll
        for (int f = 0; f < 4; f++) {
            #pragma unroll
            for (int r = 0; r < 8; r++) {
                float s, c;
                sincosf(a[f] * dm[r], &s, &c);
                const int t = f*8 + r;
                #pragma unroll
                for (int h = 0; h < 8; h++)
                    acc[h] += s * sWGs[t][h] + c * sWGc[t][h];
            }
        }
        #pragma unroll
        for (int h = 0; h < 8; h++) {
            float wg = fmaxf(acc[h], 1e-6f);
            outb[(long)h*NTOK*NTOK + j] = logf(wg);
        }
    }
}

// =====================================================================
// TF32 tensor-core GEMM core (64x64 tile, 128 threads = 4 warps 2x2,
// each warp 32x32 via m16n8k8). Y[m][c] = X[m][k]*W[c][k].
// Conflict-free smem: stride 72 -> bank = 8*lc + lr (distinct).
// =====================================================================
template<typename WriteFn>
__device__ __forceinline__ void gemm64_core(
    const float* __restrict__ X, const float* __restrict__ W,
    int m0, int n0, WriteFn&& write)
{
    __shared__ float As[16][72];   // [k][m]
    __shared__ float Bs[16][72];   // [k][n]

    const int tid = threadIdx.x;

    const int lm = tid >> 1;           // 0..63
    const int lk = (tid & 1) * 8;      // 0 or 8

    const float* Aptr = X + (long)(m0 + lm)*512 + lk;
    const float* Bptr = W + (long)(n0 + lm)*512 + lk;

    float4 xa = *(const float4*)(Aptr);
    float4 xb = *(const float4*)(Aptr + 4);
    float4 wa = *(const float4*)(Bptr);
    float4 wb = *(const float4*)(Bptr + 4);

    const int w    = tid >> 5;
    const int wm   = (w & 1) * 32;
    const int wn2  = (w >> 1) * 32;
    const int lane = tid & 31;
    const int lr   = lane >> 2;
    const int lc   = lane & 3;

    float acc[2][4][4];
    #pragma unroll
    for (int mi = 0; mi < 2; mi++)
        #pragma unroll
        for (int ni = 0; ni < 4; ni++)
            #pragma unroll
            for (int q = 0; q < 4; q++) acc[mi][ni][q] = 0.0f;

    for (int k0 = 0; k0 < 512; k0 += 16) {
        As[lk+0][lm]=f2tf32f(xa.x); As[lk+1][lm]=f2tf32f(xa.y);
        As[lk+2][lm]=f2tf32f(xa.z); As[lk+3][lm]=f2tf32f(xa.w);
        As[lk+4][lm]=f2tf32f(xb.x); As[lk+5][lm]=f2tf32f(xb.y);
        As[lk+6][lm]=f2tf32f(xb.z); As[lk+7][lm]=f2tf32f(xb.w);
        Bs[lk+0][lm]=f2tf32f(wa.x); Bs[lk+1][lm]=f2tf32f(wa.y);
        Bs[lk+2][lm]=f2tf32f(wa.z); Bs[lk+3][lm]=f2tf32f(wa.w);
        Bs[lk+4][lm]=f2tf32f(wb.x); Bs[lk+5][lm]=f2tf32f(wb.y);
        Bs[lk+6][lm]=f2tf32f(wb.z); Bs[lk+7][lm]=f2tf32f(wb.w);
        __syncthreads();

        if (k0 + 16 < 512) {
            xa = *(const float4*)(Aptr + k0 + 16);
            xb = *(const float4*)(Aptr + k0 + 20);
            wa = *(const float4*)(Bptr + k0 + 16);
            wb = *(const float4*)(Bptr + k0 + 20);
        }

        #pragma unroll
        for (int ks = 0; ks < 2; ks++) {
            const int kb = ks * 8;
            unsigned afr[2][4];
            #pragma unroll
            for (int mi = 0; mi < 2; mi++) {
                const int mrow = wm + 16*mi;
                afr[mi][0] = __float_as_uint(As[kb + lc    ][mrow + lr    ]);
                afr[mi][1] = __float_as_uint(As[kb + lc    ][mrow + lr + 8]);
                afr[mi][2] = __float_as_uint(As[kb + lc + 4][mrow + lr    ]);
                afr[mi][3] = __float_as_uint(As[kb + lc + 4][mrow + lr + 8]);
            }
            unsigned bfr[4][2];
            #pragma unroll
            for (int ni = 0; ni < 4; ni++) {
                const int ncol = wn2 + 8*ni;
                bfr[ni][0] = __float_as_uint(Bs[kb + lc    ][ncol + lr]);
                bfr[ni][1] = __float_as_uint(Bs[kb + lc + 4][ncol + lr]);
            }
            #pragma unroll
            for (int mi = 0; mi < 2; mi++)
                #pragma unroll
                for (int ni = 0; ni < 4; ni++)
                    mma_tf32(acc[mi][ni][0], acc[mi][ni][1],
                             acc[mi][ni][2], acc[mi][ni][3],
                             afr[mi][0], afr[mi][1], afr[mi][2], afr[mi][3],
                             bfr[ni][0], bfr[ni][1]);
        }
        __syncthreads();
    }

    #pragma unroll
    for (int mi = 0; mi < 2; mi++) {
        #pragma unroll
        for (int ni = 0; ni < 4; ni++) {
            const int row = wm + 16*mi + lr;
            const int col = wn2 + 8*ni + 2*lc;
            write(row,     col, acc[mi][ni][0], acc[mi][ni][1]);
            write(row + 8, col, acc[mi][ni][2], acc[mi][ni][3]);
        }
    }
}

// ---- fused QKV projection (head-split write) ----
__global__ void __launch_bounds__(128) qkv_kernel(
    const float* __restrict__ Xq, const float* __restrict__ Xk, const float* __restrict__ Xv,
    const float* __restrict__ Wq, const float* __restrict__ Wk, const float* __restrict__ Wv,
    const float* __restrict__ bq, const float* __restrict__ bk, const float* __restrict__ bv)
{
    const int z = blockIdx.z;
    const float* X    = (z == 0) ? Xq : (z == 1) ? Xk : Xv;
    const float* W    = (z == 0) ? Wq : (z == 1) ? Wk : Wv;
    const float* bias = (z == 0) ? bq : (z == 1) ? bk : bv;
    float*       Y    = (z == 0) ? g_Q : (z == 1) ? g_K : g_V;

    const int m0 = blockIdx.y * 64;
    const int n0 = blockIdx.x * 64;
    const int h  = n0 >> 6;

    gemm64_core(X, W, m0, n0,
        [&](int row, int col, float v0, float v1) {
            int m = m0 + row;
            int b = m >> 9, n = m & 511;
            float2 r;
            r.x = v0 + bias[n0 + col];
            r.y = v1 + bias[n0 + col + 1];
            *(float2*)(Y + (((long)(b*NH + h)*NTOK + n)*DKH) + col) = r;
        });
}

// ---- output projection ----
__global__ void __launch_bounds__(128) oproj_kernel(
    const float* __restrict__ W, const float* __restrict__ bias,
    float* __restrict__ Yout)
{
    const int m0 = blockIdx.y * 64;
    const int n0 = blockIdx.x * 64;

    gemm64_core(g_CTX, W, m0, n0,
        [&](int row, int col, float v0, float v1) {
            float2 r;
            r.x = v0 + bias[n0 + col];
            r.y = v1 + bias[n0 + col + 1];
            *(float2*)(Yout + (long)(m0 + row)*512 + n0 + col) = r;
        });
}

// =====================================================================
// Kernel 3: flash attention on TF32 mma. grid (B*H=32, N/64=8),
// 128 threads = 4 warps, each warp 16 q-rows. 70 KB dyn smem, 3 CTAs/SM.
// Qs/Ps stride 68 (A-operand pattern), Ks/Vs stride 72 (B-operand).
// =====================================================================
#define QS_STRIDE 68
#define KS_STRIDE 72

__global__ void __launch_bounds__(128) attn_kernel()
{
    extern __shared__ float sm[];
    float* Qs = sm;                      // [64][68]  m-major (tf32, x0.125)
    float* Ks = Qs + 64*QS_STRIDE;       // [64][72]  k-major: Ks[dk][token]
    float* Vs = Ks + 64*KS_STRIDE;       // [64][72]  token-major: Vs[token][d]
    float* Ps = Vs + 64*KS_STRIDE;       // [64][68]  m-major: Ps[m][token]

    const int tid  = threadIdx.x;
    const int lane = tid & 31;
    const int w    = tid >> 5;
    const int wm   = w * 16;       // warp's q-row base
    const int lr   = lane >> 2;
    const int lc   = lane & 3;

    const int bh = blockIdx.x;
    const int q0 = blockIdx.y * 64;

    const float* Qg = g_Q   + (long)bh*NTOK*DKH + (long)q0*DKH;
    const float* Kg = g_K   + (long)bh*NTOK*DKH;
    const float* Vg = g_V   + (long)bh*NTOK*DKH;
    const float* Bg = g_BIAS + (long)bh*NTOK*NTOK + (long)q0*NTOK;

    // load Q (64x64) m-major, tf32, fold 1/8 scale
    {
        int m = tid >> 1;
        int kq = (tid & 1) * 32;
        const float* src = Qg + m*64 + kq;
        #pragma unroll
        for (int u = 0; u < 8; u++) {
            float4 v = *(const float4*)(src + u*4);
            Qs[m*QS_STRIDE + kq + u*4 + 0] = f2tf32f(v.x * 0.125f);
            Qs[m*QS_STRIDE + kq + u*4 + 1] = f2tf32f(v.y * 0.125f);
            Qs[m*QS_STRIDE + kq + u*4 + 2] = f2tf32f(v.z * 0.125f);
            Qs[m*QS_STRIDE + kq + u*4 + 3] = f2tf32f(v.w * 0.125f);
        }
    }

    float m_i[2] = {-1e30f, -1e30f};
    float l_i[2] = {0.0f, 0.0f};
    float o[8][4];
    #pragma unroll
    for (int d = 0; d < 8; d++)
        #pragma unroll
        for (int q = 0; q < 4; q++) o[d][q] = 0.0f;

    for (int t = 0; t < 8; t++) {
        __syncthreads();   // prior tile's mma reads of Ks/Vs done (covers Q load at t=0)
        {
            int n = tid >> 1;
            int kq = (tid & 1) * 32;
            const float* srcK = Kg + (long)(t*64 + n)*64 + kq;
            const float* srcV = Vg + (long)(t*64 + n)*64 + kq;
            #pragma unroll
            for (int u = 0; u < 8; u++) {
                float4 v = *(const float4*)(srcK + u*4);
                Ks[(kq+u*4+0)*KS_STRIDE + n] = f2tf32f(v.x);
                Ks[(kq+u*4+1)*KS_STRIDE + n] = f2tf32f(v.y);
                Ks[(kq+u*4+2)*KS_STRIDE + n] = f2tf32f(v.z);
                Ks[(kq+u*4+3)*KS_STRIDE + n] = f2tf32f(v.w);
                float4 vv = *(const float4*)(srcV + u*4);
                float4 cv;
                cv.x = f2tf32f(vv.x); cv.y = f2tf32f(vv.y);
                cv.z = f2tf32f(vv.z); cv.w = f2tf32f(vv.w);
                *(float4*)&Vs[n*KS_STRIDE + kq + u*4] = cv;
            }
        }
        __syncthreads();

        // ---- S = (Q/8) . K^T via mma: warp tile m16 x n64 ----
        float sacc[8][4];
        #pragma unroll
        for (int nc = 0; nc < 8; nc++)
            #pragma unroll
            for (int q = 0; q < 4; q++) sacc[nc][q] = 0.0f;

        #pragma unroll
        for (int ks = 0; ks < 8; ks++) {
            const int kb = ks * 8;
            unsigned a0 = __float_as_uint(Qs[(wm+lr  )*QS_STRIDE + kb + lc    ]);
            unsigned a1 = __float_as_uint(Qs[(wm+lr+8)*QS_STRIDE + kb + lc    ]);
            unsigned a2 = __float_as_uint(Qs[(wm+lr  )*QS_STRIDE + kb + lc + 4]);
            unsigned a3 = __float_as_uint(Qs[(wm+lr+8)*QS_STRIDE + kb + lc + 4]);
            #pragma unroll
            for (int nc = 0; nc < 8; nc++) {
                unsigned b0 = __float_as_uint(Ks[(kb+lc  )*KS_STRIDE + 8*nc + lr]);
                unsigned b1 = __float_as_uint(Ks[(kb+lc+4)*KS_STRIDE + 8*nc + lr]);
                mma_tf32(sacc[nc][0], sacc[nc][1], sacc[nc][2], sacc[nc][3],
                         a0, a1, a2, a3, b0, b1);
            }
        }

        // ---- add bias ----
        const float* brow0 = Bg + (long)(wm+lr  )*512 + t*64;
        const float* brow1 = Bg + (long)(wm+lr+8)*512 + t*64;
        #pragma unroll
        for (int nc = 0; nc < 8; nc++) {
            float2 b0 = *(const float2*)(brow0 + 8*nc + 2*lc);
            float2 b1 = *(const float2*)(brow1 + 8*nc + 2*lc);
            sacc[nc][0] += b0.x; sacc[nc][1] += b0.y;
            sacc[nc][2] += b1.x; sacc[nc][3] += b1.y;
        }

        // ---- online softmax (rows lr and lr+8; 4 threads per row: xor 1,2) ----
        #pragma unroll
        for (int i = 0; i < 2; i++) {
            float tm = -1e30f;
            #pragma unroll
            for (int nc = 0; nc < 8; nc++)
                tm = fmaxf(tm, fmaxf(sacc[nc][2*i], sacc[nc][2*i+1]));
            tm = fmaxf(tm, __shfl_xor_sync(0xffffffffu, tm, 1));
            tm = fmaxf(tm, __shfl_xor_sync(0xffffffffu, tm, 2));
            float mnew = fmaxf(m_i[i], tm);
            float scale = __expf(m_i[i] - mnew);
            m_i[i] = mnew;

            float s = 0.0f;
            #pragma unroll
            for (int nc = 0; nc < 8; nc++) {
                float p0 = __expf(sacc[nc][2*i]   - mnew);
                float p1 = __expf(sacc[nc][2*i+1] - mnew);
                sacc[nc][2*i]   = p0;
                sacc[nc][2*i+1] = p1;
                s += p0 + p1;
            }
            s += __shfl_xor_sync(0xffffffffu, s, 1);
            s += __shfl_xor_sync(0xffffffffu, s, 2);
            l_i[i] = l_i[i]*scale + s;

            #pragma unroll
            for (int d = 0; d < 8; d++) {
                o[d][2*i]   *= scale;
                o[d][2*i+1] *= scale;
            }
        }

        // ---- stash P (tf32) in smem for A-operand reload ----
        #pragma unroll
        for (int nc = 0; nc < 8; nc++) {
            float2 p0, p1;
            p0.x = f2tf32f(sacc[nc][0]); p0.y = f2tf32f(sacc[nc][1]);
            p1.x = f2tf32f(sacc[nc][2]); p1.y = f2tf32f(sacc[nc][3]);
            *(float2*)&Ps[(wm+lr  )*QS_STRIDE + 8*nc + 2*lc] = p0;
            *(float2*)&Ps[(wm+lr+8)*QS_STRIDE + 8*nc + 2*lc] = p1;
        }
        __syncwarp();   // Ps rows are warp-private; warp-level ordering suffices

        // ---- O += P . V ----
        #pragma unroll
        for (int ks = 0; ks < 8; ks++) {
            const int kb = ks * 8;
            unsigned a0 = __float_as_uint(Ps[(wm+lr  )*QS_STRIDE + kb + lc    ]);
            unsigned a1 = __float_as_uint(Ps[(wm+lr+8)*QS_STRIDE + kb + lc    ]);
            unsigned a2 = __float_as_uint(Ps[(wm+lr  )*QS_STRIDE + kb + lc + 4]);
            unsigned a3 = __float_as_uint(Ps[(wm+lr+8)*QS_STRIDE + kb + lc + 4]);
            #pragma unroll
            for (int dc = 0; dc < 8; dc++) {
                unsigned b0 = __float_as_uint(Vs[(kb+lc  )*KS_STRIDE + 8*dc + lr]);
                unsigned b1 = __float_as_uint(Vs[(kb+lc+4)*KS_STRIDE + 8*dc + lr]);
                mma_tf32(o[dc][0], o[dc][1], o[dc][2], o[dc][3],
                         a0, a1, a2, a3, b0, b1);
            }
        }
    }

    // ---- normalize + write ----
    const int b = bh >> 3, h = bh & 7;
    const float inv0 = 1.0f / l_i[0];
    const float inv1 = 1.0f / l_i[1];
    float* ctx0 = g_CTX + ((long)(b*NTOK + q0 + wm + lr    ))*512 + h*64;
    float* ctx1 = g_CTX + ((long)(b*NTOK + q0 + wm + lr + 8))*512 + h*64;
    #pragma unroll
    for (int dc = 0; dc < 8; dc++) {
        float2 r0, r1;
        r0.x = o[dc][0]*inv0; r0.y = o[dc][1]*inv0;
        r1.x = o[dc][2]*inv1; r1.y = o[dc][3]*inv1;
        *(float2*)(ctx0 + 8*dc + 2*lc) = r0;
        *(float2*)(ctx1 + 8*dc + 2*lc) = r1;
    }
}

// =====================================================================
// launch
// =====================================================================
extern "C" void kernel_launch(void* const* d_in, const int* in_sizes, int n_in,
                              void* d_out, int out_size)
{
    const float* in_q  = (const float*)d_in[0];
    const float* in_k  = (const float*)d_in[1];
    const float* in_v  = (const float*)d_in[2];
    const float* box   = (const float*)d_in[3];
    const float* Wq    = (const float*)d_in[4];
    const float* bq    = (const float*)d_in[5];
    const float* Wk    = (const float*)d_in[6];
    const float* bk    = (const float*)d_in[7];
    const float* Wv    = (const float*)d_in[8];
    const float* bv    = (const float*)d_in[9];
    const float* Wo    = (const float*)d_in[10];
    const float* bo    = (const float*)d_in[11];
    const float* WG    = (const float*)d_in[12];
    const float* bG    = (const float*)d_in[13];
    float* out = (float*)d_out;

    const int ATTN_SMEM = (2*64*QS_STRIDE + 2*64*KS_STRIDE) * (int)sizeof(float); // 71680
    cudaFuncSetAttribute(attn_kernel, cudaFuncAttributeMaxDynamicSharedMemorySize, ATTN_SMEM);

    // geometry bias
    geom_kernel<<<dim3(NTOK, BATCH), 256>>>(box, WG, bG);

    // fused Q/K/V projections (tf32 tensor cores, 64x64 tiles, 768 CTAs)
    qkv_kernel<<<dim3(512/64, 2048/64, 3), 128>>>(in_q, in_k, in_v,
                                                  Wq, Wk, Wv, bq, bk, bv);

    // attention (tf32 tensor cores)
    attn_kernel<<<dim3(BATCH*NH, NTOK/64), 128, ATTN_SMEM>>>();

    // output projection -> d_out
    oproj_kernel<<<dim3(512/64, 2048/64), 128>>>(Wo, bo, out);
}